// round 11
// baseline (speedup 1.0000x reference)
#include <cuda_runtime.h>
#include <cstdint>

// out[b, bin, d] = ce[chr[b]-1, d]
// BS=512, BINS=2001, DIM=128, N_CHR=24
// Pure store-bandwidth kernel: 512*2001*128*4B = 524.5 MB written.
//
// FINAL (converged, reverted from persistent-grid experiment):
// multi-wave launch (8192 short CTAs) + .cs float4 streaming stores + 2x
// unroll. Measured 73.8-74.2us @ 6.43-6.48 TB/s HBM (~81% of spec).
// Evidence of convergence:
//  - store width (f4 vs v8) : neutral
//  - cache policy (.cs)     : neutral (+0.1%)
//  - persistent 1-wave grid : REGRESSED to 86us (tail imbalance, DRAM 71%)
// => chip write-stream ceiling; HW work-steal scheduler beats persistence.

static constexpr int BS = 512;
static constexpr int BINS = 2001;
static constexpr int DIM = 128;            // 32 float4 per row
static constexpr int THREADS = 256;        // 8 bins per iteration
static constexpr int CHUNKS = 16;          // bin-chunks per sample
static constexpr int BINS_PER_CHUNK = (BINS + CHUNKS - 1) / CHUNKS;  // 126

__device__ __forceinline__ void stcs4(float4* p, const float4& v) {
    asm volatile("st.global.cs.v4.f32 [%0], {%1, %2, %3, %4};"
                 :: "l"(p), "f"(v.x), "f"(v.y), "f"(v.z), "f"(v.w)
                 : "memory");
}

__global__ __launch_bounds__(THREADS)
void chrom_embed_kernel(const int* __restrict__ chr,
                        const float4* __restrict__ ce4,   // [24, 32] float4
                        float4* __restrict__ out4)        // [512, 2001, 32] float4
{
    const int b     = blockIdx.y;
    const int chunk = blockIdx.x;

    const int row = chr[b] - 1;                 // 0..23
    const int col = threadIdx.x & 31;           // float4 column within the row
    const int binOfs = threadIdx.x >> 5;        // 0..7 (warp id)

    // Broadcast load of this sample's embedding row (one float4/thread).
    const float4 v = ce4[row * (DIM / 4) + col];

    const int binStart = chunk * BINS_PER_CHUNK;
    int binEnd = binStart + BINS_PER_CHUNK;
    if (binEnd > BINS) binEnd = BINS;

    float4* __restrict__ dst = out4 + (size_t)b * BINS * (DIM / 4) + col;

    constexpr int STEP = THREADS / 32;   // 8 bins per iteration
    int bin = binStart + binOfs;

    // 2x unrolled: two independent streaming stores in flight per warp slot.
    for (; bin + STEP < binEnd; bin += 2 * STEP) {
        stcs4(dst + (size_t)bin * (DIM / 4), v);
        stcs4(dst + (size_t)(bin + STEP) * (DIM / 4), v);
    }
    if (bin < binEnd) {
        stcs4(dst + (size_t)bin * (DIM / 4), v);
    }
}

extern "C" void kernel_launch(void* const* d_in, const int* in_sizes, int n_in,
                              void* d_out, int out_size)
{
    // Inputs per reference order: tensor [512,2001] f32 (unused),
    // chr [512] int32, ce [24,128] f32.
    const int*    chr = (const int*)d_in[1];
    const float4* ce4 = (const float4*)d_in[2];
    float4*       out = (float4*)d_out;

    dim3 grid(CHUNKS, BS);
    chrom_embed_kernel<<<grid, THREADS>>>(chr, ce4, out);
}

// round 12
// speedup vs baseline: 1.3545x; 1.3545x over previous
#include <cuda_runtime.h>
#include <cstdint>

// out[b, bin, d] = ce[chr[b]-1, d]
// BS=512, BINS=2001, DIM=128, N_CHR=24
// Pure store-bandwidth kernel: 512*2001*128*4B = 524.5 MB written.
//
// FINAL (converged): multi-wave launch (8192 short CTAs) + .cs float4
// streaming stores + 2x unroll. Clean-run measurements: 73.76-74.24us @
// 6.43-6.48 TB/s HBM (~81% of spec = pure-write ceiling).
// Variant evidence:
//  - store width (f4 vs v8) : neutral
//  - cache policy (.cs)     : neutral (+0.1%)
//  - persistent 1-wave grid : REGRESSED (86us, tail imbalance, DRAM 71%)
//  - R11 100us reading      : environment (HBM 4.54 TB/s chip-wide; same SASS)
// => kernel is at the chip write-stream ceiling; resubmitted unchanged.

static constexpr int BS = 512;
static constexpr int BINS = 2001;
static constexpr int DIM = 128;            // 32 float4 per row
static constexpr int THREADS = 256;        // 8 bins per iteration
static constexpr int CHUNKS = 16;          // bin-chunks per sample
static constexpr int BINS_PER_CHUNK = (BINS + CHUNKS - 1) / CHUNKS;  // 126

__device__ __forceinline__ void stcs4(float4* p, const float4& v) {
    asm volatile("st.global.cs.v4.f32 [%0], {%1, %2, %3, %4};"
                 :: "l"(p), "f"(v.x), "f"(v.y), "f"(v.z), "f"(v.w)
                 : "memory");
}

__global__ __launch_bounds__(THREADS)
void chrom_embed_kernel(const int* __restrict__ chr,
                        const float4* __restrict__ ce4,   // [24, 32] float4
                        float4* __restrict__ out4)        // [512, 2001, 32] float4
{
    const int b     = blockIdx.y;
    const int chunk = blockIdx.x;

    const int row = chr[b] - 1;                 // 0..23
    const int col = threadIdx.x & 31;           // float4 column within the row
    const int binOfs = threadIdx.x >> 5;        // 0..7 (warp id)

    // Broadcast load of this sample's embedding row (one float4/thread).
    const float4 v = ce4[row * (DIM / 4) + col];

    const int binStart = chunk * BINS_PER_CHUNK;
    int binEnd = binStart + BINS_PER_CHUNK;
    if (binEnd > BINS) binEnd = BINS;

    float4* __restrict__ dst = out4 + (size_t)b * BINS * (DIM / 4) + col;

    constexpr int STEP = THREADS / 32;   // 8 bins per iteration
    int bin = binStart + binOfs;

    // 2x unrolled: two independent streaming stores in flight per warp slot.
    for (; bin + STEP < binEnd; bin += 2 * STEP) {
        stcs4(dst + (size_t)bin * (DIM / 4), v);
        stcs4(dst + (size_t)(bin + STEP) * (DIM / 4), v);
    }
    if (bin < binEnd) {
        stcs4(dst + (size_t)bin * (DIM / 4), v);
    }
}

extern "C" void kernel_launch(void* const* d_in, const int* in_sizes, int n_in,
                              void* d_out, int out_size)
{
    // Inputs per reference order: tensor [512,2001] f32 (unused),
    // chr [512] int32, ce [24,128] f32.
    const int*    chr = (const int*)d_in[1];
    const float4* ce4 = (const float4*)d_in[2];
    float4*       out = (float4*)d_out;

    dim3 grid(CHUNKS, BS);
    chrom_embed_kernel<<<grid, THREADS>>>(chr, ce4, out);
}